// round 2
// baseline (speedup 1.0000x reference)
#include <cuda_runtime.h>

// entmax-1.5 attention, B=2 H=8 S=2048 D=64, fp32.
// CTA = 16 queries (8 warps x 2 queries). Scores resident in smem.
// tau via Newton (monotone convergent from below for convex f).
// Pass 2 exploits entmax sparsity: whole 128-key V chunks skipped when no
// query in the CTA has support there.

#define S_LEN   2048
#define D_DIM   64
#define TQ      16
#define CK      128
#define KSTRIDE 65          // 65-float row stride -> conflict-free scalar LDS
#define NTHREADS 256
#define NCHUNK  (S_LEN / CK)   // 16
#define NEWTON_ITERS 25

// dynamic smem layout (floats):
//   Qsm   [TQ * D_DIM]          = 1024
//   KV    [CK * KSTRIDE]        = 8320   (K tile in pass 1, V tile in pass 2)
//   Sc    [TQ * S_LEN]          = 32768  (score buffer, raw scaled scores)
#define SMEM_FLOATS (TQ * D_DIM + CK * KSTRIDE + TQ * S_LEN)

// Solve for thr = mx + 2*tau such that sum_i clip((s_i - thr)/2, 0)^2 = 1.
// row[j*32 + lane] covers all 2048 scores of one query across the warp.
__device__ __forceinline__ float solve_thr(const float* __restrict__ row, int lane)
{
    float x[64];
    float mx = -1e30f;
#pragma unroll
    for (int j = 0; j < 64; j++) {
        x[j] = row[j * 32 + lane];
        mx = fmaxf(mx, x[j]);
    }
#pragma unroll
    for (int off = 16; off; off >>= 1)
        mx = fmaxf(mx, __shfl_xor_sync(0xffffffffu, mx, off));
#pragma unroll
    for (int j = 0; j < 64; j++)
        x[j] = (x[j] - mx) * 0.5f;   // x in (-inf, 0], max = 0

    float tau = -1.0f;               // f(-1) >= (0+1)^2 = 1 -> tau0 <= tau*
    for (int it = 0; it < NEWTON_ITERS; it++) {
        float f = 0.0f, g = 0.0f;
#pragma unroll
        for (int j = 0; j < 64; j++) {
            float m = fmaxf(x[j] - tau, 0.0f);
            f = fmaf(m, m, f);
            g += m;
        }
#pragma unroll
        for (int off = 16; off; off >>= 1) {
            f += __shfl_xor_sync(0xffffffffu, f, off);
            g += __shfl_xor_sync(0xffffffffu, g, off);
        }
        // f convex decreasing, f' = -2g, g >= -tau > 0 while below root
        tau += (f - 1.0f) / (2.0f * g);
    }
    return mx + 2.0f * tau;   // p_i = clip((s_i - thr)*0.5, 0)^2
}

__global__ void __launch_bounds__(NTHREADS, 1)
entmax_attn_kernel(const float* __restrict__ q, const float* __restrict__ k,
                   const float* __restrict__ v, float* __restrict__ out)
{
    extern __shared__ float smem[];
    float* Qsm = smem;
    float* KV  = smem + TQ * D_DIM;
    float* Sc  = KV + CK * KSTRIDE;
    __shared__ int flags[NCHUNK];

    const int tid  = threadIdx.x;
    const int warp = tid >> 5;
    const int lane = tid & 31;

    const int bh = blockIdx.z * gridDim.y + blockIdx.y;
    const size_t base = (size_t)bh * S_LEN * D_DIM;
    const int q0 = blockIdx.x * TQ;

    // ---- load Q tile (16x64) ----
    {
        const float4* qg = (const float4*)(q + base + (size_t)q0 * D_DIM);
        ((float4*)Qsm)[tid] = qg[tid];   // 256 float4 = 1024 floats
    }
    __syncthreads();

    const int qa = warp * 2;
    const int qb = qa + 1;

    // q rows in registers (broadcast LDS, conflict-free)
    float qra[D_DIM], qrb[D_DIM];
#pragma unroll
    for (int d = 0; d < D_DIM; d++) {
        qra[d] = Qsm[qa * D_DIM + d];
        qrb[d] = Qsm[qb * D_DIM + d];
    }

    const float scale = 0.125f;  // 1/sqrt(64)

    // ---- pass 1: scores = scale * Q K^T, stored to Sc ----
    for (int c = 0; c < NCHUNK; c++) {
        __syncthreads();  // previous chunk fully consumed before overwrite
        {
            const float4* kg = (const float4*)(k + base + (size_t)c * CK * D_DIM);
#pragma unroll
            for (int j = 0; j < (CK * D_DIM / 4) / NTHREADS; j++) {  // 8
                int idx = tid + j * NTHREADS;          // float4 index
                float4 val = kg[idx];
                int key = idx >> 4;                    // row (16 float4/row)
                int d4  = (idx & 15) << 2;
                float* dst = &KV[key * KSTRIDE + d4];
                dst[0] = val.x; dst[1] = val.y; dst[2] = val.z; dst[3] = val.w;
            }
        }
        __syncthreads();
#pragma unroll
        for (int kk = 0; kk < CK / 32; kk++) {
            int r = kk * 32 + lane;
            const float* krow = &KV[r * KSTRIDE];
            float sa = 0.0f, sb = 0.0f;
#pragma unroll
            for (int d = 0; d < D_DIM; d++) {
                float kv = krow[d];
                sa = fmaf(qra[d], kv, sa);
                sb = fmaf(qrb[d], kv, sb);
            }
            Sc[qa * S_LEN + c * CK + r] = sa * scale;
            Sc[qb * S_LEN + c * CK + r] = sb * scale;
        }
    }
    __syncthreads();

    if (tid < NCHUNK) flags[tid] = 0;

    // ---- entmax threshold per query (Newton, register-resident) ----
    const float* rowa = Sc + qa * S_LEN;
    const float* rowb = Sc + qb * S_LEN;
    float thr_a = solve_thr(rowa, lane);
    float thr_b = solve_thr(rowb, lane);

    __syncthreads();  // flags init visible to all

    // ---- mark chunks with any support (sparsity skip) ----
#pragma unroll
    for (int j = 0; j < 64; j++) {
        int col = j * 32 + lane;
        bool nz = (rowa[col] > thr_a) || (rowb[col] > thr_b);
        if (__ballot_sync(0xffffffffu, nz)) flags[j >> 2] = 1;  // j>>2 == chunk
    }
    __syncthreads();

    // ---- pass 2: out = P V, only over flagged chunks ----
    float acc_a[D_DIM], acc_b[D_DIM];
#pragma unroll
    for (int d = 0; d < D_DIM; d++) { acc_a[d] = 0.0f; acc_b[d] = 0.0f; }

    for (int c = 0; c < NCHUNK; c++) {
        if (!flags[c]) continue;      // uniform across block
        __syncthreads();
        {
            const float4* vg = (const float4*)(v + base + (size_t)c * CK * D_DIM);
#pragma unroll
            for (int j = 0; j < (CK * D_DIM / 4) / NTHREADS; j++) {
                int idx = tid + j * NTHREADS;
                float4 val = vg[idx];
                int key = idx >> 4;
                int d4  = (idx & 15) << 2;
                float* dst = &KV[key * KSTRIDE + d4];
                dst[0] = val.x; dst[1] = val.y; dst[2] = val.z; dst[3] = val.w;
            }
        }
        __syncthreads();
#pragma unroll
        for (int kk = 0; kk < CK / 32; kk++) {
            int r = kk * 32 + lane;
            int col = c * CK + r;
            float ma = fmaxf((rowa[col] - thr_a) * 0.5f, 0.0f);
            float mb = fmaxf((rowb[col] - thr_b) * 0.5f, 0.0f);
            float pa = ma * ma, pb = mb * mb;
            if (__any_sync(0xffffffffu, (pa > 0.0f) || (pb > 0.0f))) {
                const float* vrow = &KV[r * KSTRIDE];
#pragma unroll
                for (int d = 0; d < D_DIM; d++) {
                    float vv = vrow[d];
                    acc_a[d] = fmaf(pa, vv, acc_a[d]);
                    acc_b[d] = fmaf(pb, vv, acc_b[d]);
                }
            }
        }
    }

    // ---- reduce across lanes, write out ----
#pragma unroll
    for (int off = 16; off; off >>= 1) {
#pragma unroll
        for (int d = 0; d < D_DIM; d++) {
            acc_a[d] += __shfl_down_sync(0xffffffffu, acc_a[d], off);
            acc_b[d] += __shfl_down_sync(0xffffffffu, acc_b[d], off);
        }
    }
    if (lane == 0) {
        float4* oa = (float4*)(out + base + (size_t)(q0 + qa) * D_DIM);
        float4* ob = (float4*)(out + base + (size_t)(q0 + qb) * D_DIM);
#pragma unroll
        for (int d4 = 0; d4 < D_DIM / 4; d4++) {
            oa[d4] = make_float4(acc_a[4*d4+0], acc_a[4*d4+1], acc_a[4*d4+2], acc_a[4*d4+3]);
            ob[d4] = make_float4(acc_b[4*d4+0], acc_b[4*d4+1], acc_b[4*d4+2], acc_b[4*d4+3]);
        }
    }
}

extern "C" void kernel_launch(void* const* d_in, const int* in_sizes, int n_in,
                              void* d_out, int out_size)
{
    const float* q = (const float*)d_in[0];
    const float* k = (const float*)d_in[1];
    const float* v = (const float*)d_in[2];
    float* out = (float*)d_out;

    const size_t smem_bytes = (size_t)SMEM_FLOATS * sizeof(float);  // ~168 KB
    cudaFuncSetAttribute(entmax_attn_kernel,
                         cudaFuncAttributeMaxDynamicSharedMemorySize,
                         (int)smem_bytes);

    dim3 grid(S_LEN / TQ, 8 /*H*/, 2 /*B*/);
    entmax_attn_kernel<<<grid, NTHREADS, smem_bytes>>>(q, k, v, out);
}

// round 4
// speedup vs baseline: 1.7037x; 1.7037x over previous
#include <cuda_runtime.h>

// entmax-1.5 attention, B=2 H=8 S=2048 D=64, fp32. Two-kernel design:
//   k1: scores = scale * Q K^T  -> 256MB __device__ scratch (warp-row GEMM,
//       4 queries/warp via lane-pair D-split, double-buffered K chunks)
//   k2: per-row entmax (Newton + active-set compaction) + sparse P*V

#define SL   2048
#define DD   64
#define NBH  16
#define CK   128
#define KPAD 68          // floats per K row in smem (16B-aligned, distinct 16B units)
#define TQ   32          // queries per CTA in k1 (8 warps x 4)
#define NT1  256

#define NEWTON_FULL    6
#define NEWTON_COMPACT 18
#define CCAP           8
#define CAPL           224   // per-warp support list capacity (batched flush)

__device__ float g_scores[(size_t)NBH * SL * SL];   // 256 MiB scratch

// ---------------------------------------------------------------------------
// Kernel 1: scores GEMM
// ---------------------------------------------------------------------------
__global__ void __launch_bounds__(NT1, 1)
qk_scores_kernel(const float* __restrict__ q, const float* __restrict__ k)
{
    extern __shared__ float smem[];
    float* Qsm = smem;                         // TQ*DD = 2048 floats
    float* Ks0 = smem + TQ * DD;               // CK*KPAD
    float* Ks1 = Ks0 + CK * KPAD;

    const int tid  = threadIdx.x;
    const int warp = tid >> 5;
    const int lane = tid & 31;
    const int half = lane & 1;                 // which 32-d half this lane owns
    const int pair = lane >> 1;                // 0..15

    const int bh = blockIdx.y;
    const size_t base = (size_t)bh * SL * DD;
    const int q0 = blockIdx.x * TQ;
    float* __restrict__ sc = g_scores + (size_t)bh * SL * SL;

    // load Q tile (32 x 64 = 512 float4)
    {
        const float4* qg = (const float4*)(q + base + (size_t)q0 * DD);
        ((float4*)Qsm)[tid] = qg[tid];
        ((float4*)Qsm)[tid + NT1] = qg[tid + NT1];
    }

    // preload K chunk 0
    {
        const float4* kg = (const float4*)(k + base);
#pragma unroll
        for (int u = 0; u < 8; u++) {
            int idx = tid + u * NT1;
            float4 val = kg[idx];
            int row = idx >> 4, d4 = (idx & 15) << 2;
            *(float4*)&Ks0[row * KPAD + d4] = val;
        }
    }
    __syncthreads();

    // q registers: 4 queries x 32 d-half
    const int qbase = warp * 4;
    float qr[4][32];
#pragma unroll
    for (int i = 0; i < 4; i++)
#pragma unroll
        for (int d = 0; d < 32; d++)
            qr[i][d] = Qsm[(qbase + i) * DD + half * 32 + d];

    const float scale = 0.125f;

    for (int c = 0; c < SL / CK; c++) {
        float* cur = (c & 1) ? Ks1 : Ks0;
        float* nxt = (c & 1) ? Ks0 : Ks1;

        // prefetch next chunk into registers (latency hidden by compute)
        float4 pf[8];
        if (c < SL / CK - 1) {
            const float4* kg = (const float4*)(k + base + (size_t)(c + 1) * CK * DD);
#pragma unroll
            for (int u = 0; u < 8; u++) pf[u] = kg[tid + u * NT1];
        }

#pragma unroll
        for (int kk = 0; kk < 8; kk++) {
            const float4* kr = (const float4*)&cur[(kk * 16 + pair) * KPAD + half * 32];
            float kv[32];
#pragma unroll
            for (int u = 0; u < 8; u++) ((float4*)kv)[u] = kr[u];

            float s0 = 0.f, s1 = 0.f, s2 = 0.f, s3 = 0.f;
#pragma unroll
            for (int d = 0; d < 32; d++) {
                float kd = kv[d];
                s0 = fmaf(qr[0][d], kd, s0);
                s1 = fmaf(qr[1][d], kd, s1);
                s2 = fmaf(qr[2][d], kd, s2);
                s3 = fmaf(qr[3][d], kd, s3);
            }
            s0 += __shfl_xor_sync(0xffffffffu, s0, 1);
            s1 += __shfl_xor_sync(0xffffffffu, s1, 1);
            s2 += __shfl_xor_sync(0xffffffffu, s2, 1);
            s3 += __shfl_xor_sync(0xffffffffu, s3, 1);

            int key = c * CK + kk * 16 + pair;
            if (half == 0) {
                sc[(size_t)(q0 + qbase + 0) * SL + key] = s0 * scale;
                sc[(size_t)(q0 + qbase + 1) * SL + key] = s1 * scale;
            } else {
                sc[(size_t)(q0 + qbase + 2) * SL + key] = s2 * scale;
                sc[(size_t)(q0 + qbase + 3) * SL + key] = s3 * scale;
            }
        }

        if (c < SL / CK - 1) {
            __syncthreads();   // all warps done reading nxt's old contents
#pragma unroll
            for (int u = 0; u < 8; u++) {
                int idx = tid + u * NT1;
                int row = idx >> 4, d4 = (idx & 15) << 2;
                *(float4*)&nxt[row * KPAD + d4] = pf[u];
            }
            __syncthreads();
        }
    }
}

// ---------------------------------------------------------------------------
// Kernel 2: entmax (Newton + compaction) + sparse P*V. One warp per row.
// ---------------------------------------------------------------------------
__global__ void __launch_bounds__(256, 2)
entmax_pv_kernel(const float* __restrict__ v, float* __restrict__ out)
{
    __shared__ float sp[8][CAPL];
    __shared__ int   si[8][CAPL];

    const int tid  = threadIdx.x;
    const int warp = tid >> 5;
    const int lane = tid & 31;

    const int gw = blockIdx.x * 8 + warp;       // global row id, 0..32767
    const int bh = gw >> 11;
    const int qi = gw & (SL - 1);

    const float* __restrict__ srow = g_scores + ((size_t)bh * SL + qi) * SL;
    const float* __restrict__ vb   = v + (size_t)bh * SL * DD;

    // load 2048 scores into 64 regs/lane; x[jj*4+c] <-> col 128*jj + 4*lane + c
    float x[64];
    float mx = -1e30f;
#pragma unroll
    for (int jj = 0; jj < 16; jj++) {
        float4 t = ((const float4*)srow)[jj * 32 + lane];
        x[jj * 4 + 0] = t.x; x[jj * 4 + 1] = t.y;
        x[jj * 4 + 2] = t.z; x[jj * 4 + 3] = t.w;
        mx = fmaxf(mx, fmaxf(fmaxf(t.x, t.y), fmaxf(t.z, t.w)));
    }
#pragma unroll
    for (int off = 16; off; off >>= 1)
        mx = fmaxf(mx, __shfl_xor_sync(0xffffffffu, mx, off));
#pragma unroll
    for (int j = 0; j < 64; j++) x[j] = (x[j] - mx) * 0.5f;

    // Newton from below (tau0 = -1 guarantees f(tau0) >= 1)
    float tau = -1.0f;
    for (int it = 0; it < NEWTON_FULL; it++) {
        float f = 0.f, g = 0.f;
#pragma unroll
        for (int j = 0; j < 64; j++) {
            float m = fmaxf(x[j] - tau, 0.f);
            f = fmaf(m, m, f); g += m;
        }
#pragma unroll
        for (int off = 16; off; off >>= 1) {
            f += __shfl_xor_sync(0xffffffffu, f, off);
            g += __shfl_xor_sync(0xffffffffu, g, off);
        }
        tau += (f - 1.0f) / fmaxf(2.0f * g, 1e-20f);
    }

    // compact active set (x > tau) into a shift register of CCAP values
    float cv[CCAP];
#pragma unroll
    for (int i = 0; i < CCAP; i++) cv[i] = -1e30f;
    int cnt = 0;
#pragma unroll
    for (int j = 0; j < 64; j++) {
        if (x[j] > tau) {
#pragma unroll
            for (int i = CCAP - 1; i > 0; i--) cv[i] = cv[i - 1];
            cv[0] = x[j];
            cnt++;
        }
    }
    bool ovf = __ballot_sync(0xffffffffu, cnt > CCAP) != 0u;

    if (!ovf) {
        for (int it = 0; it < NEWTON_COMPACT; it++) {
            float f = 0.f, g = 0.f;
#pragma unroll
            for (int i = 0; i < CCAP; i++) {
                float m = fmaxf(cv[i] - tau, 0.f);   // inactive slots are -1e30
                f = fmaf(m, m, f); g += m;
            }
#pragma unroll
            for (int off = 16; off; off >>= 1) {
                f += __shfl_xor_sync(0xffffffffu, f, off);
                g += __shfl_xor_sync(0xffffffffu, g, off);
            }
            tau += (f - 1.0f) / fmaxf(2.0f * g, 1e-20f);
        }
    } else {
        for (int it = 0; it < NEWTON_COMPACT; it++) {
            float f = 0.f, g = 0.f;
#pragma unroll
            for (int j = 0; j < 64; j++) {
                float m = fmaxf(x[j] - tau, 0.f);
                f = fmaf(m, m, f); g += m;
            }
#pragma unroll
            for (int off = 16; off; off >>= 1) {
                f += __shfl_xor_sync(0xffffffffu, f, off);
                g += __shfl_xor_sync(0xffffffffu, g, off);
            }
            tau += (f - 1.0f) / fmaxf(2.0f * g, 1e-20f);
        }
    }

    // extract support into per-warp smem list (batched), then gather V
    float acc0 = 0.f, acc1 = 0.f;
    const unsigned ltmask = (1u << lane) - 1u;
    int off = 0;

#pragma unroll 4
    for (int j = 0; j < 64; j++) {
        float m = fmaxf(x[j] - tau, 0.f);
        unsigned mask = __ballot_sync(0xffffffffu, m > 0.f);
        int c = __popc(mask);
        if (off + c > CAPL) {                    // uniform: flush batch
            __syncwarp();
            for (int t = 0; t < off; t++) {
                float pv = sp[warp][t];
                int key  = si[warp][t];
                acc0 = fmaf(pv, vb[key * DD + lane], acc0);
                acc1 = fmaf(pv, vb[key * DD + 32 + lane], acc1);
            }
            __syncwarp();
            off = 0;
        }
        if (m > 0.f) {
            int pos = off + __popc(mask & ltmask);
            sp[warp][pos] = m * m;
            si[warp][pos] = 128 * (j >> 2) + 4 * lane + (j & 3);
        }
        off += c;
    }
    __syncwarp();
    for (int t = 0; t < off; t++) {
        float pv = sp[warp][t];
        int key  = si[warp][t];
        acc0 = fmaf(pv, vb[key * DD + lane], acc0);
        acc1 = fmaf(pv, vb[key * DD + 32 + lane], acc1);
    }

    float* orow = out + ((size_t)bh * SL + qi) * DD;
    orow[lane]      = acc0;
    orow[lane + 32] = acc1;
}

// ---------------------------------------------------------------------------
extern "C" void kernel_launch(void* const* d_in, const int* in_sizes, int n_in,
                              void* d_out, int out_size)
{
    const float* q = (const float*)d_in[0];
    const float* k = (const float*)d_in[1];
    const float* v = (const float*)d_in[2];
    float* out = (float*)d_out;

    const size_t smem1 = (size_t)(TQ * DD + 2 * CK * KPAD) * sizeof(float); // ~77.8KB
    cudaFuncSetAttribute(qk_scores_kernel,
                         cudaFuncAttributeMaxDynamicSharedMemorySize, (int)smem1);

    dim3 g1(SL / TQ, NBH);
    qk_scores_kernel<<<g1, NT1, smem1>>>(q, k);

    entmax_pv_kernel<<<(NBH * SL) / 8, 256>>>(v, out);
}

// round 6
// speedup vs baseline: 2.7703x; 1.6261x over previous
#include <cuda_runtime.h>
#include <cuda_bf16.h>
#include <cstdint>

// entmax-1.5 attention, B=2 H=8 S=2048 D=64 fp32.
//  prep: Q,K fp32 -> bf16 hi/lo concat (K=192 trick: [Qh|Qh|Ql] x [Kh|Kl|Kh])
//  k1:   HMMA (mma.sync bf16) GEMM M=128/CTA, K=192 -> g_scores fp32 (256MB)
//  k2:   per-row entmax (2 warps/row, Newton + closed-form) + sparse P*V

#define SL   2048
#define DD   64
#define NBH  16
#define KCAT 192
#define RB   400        // smem row stride bytes (25 x 16B, odd -> ldmatrix conflict-free)

__device__ float4 g_scores4[(size_t)NBH * SL * SL / 4];      // 256 MiB
__device__ uint4  g_qcat4[(size_t)NBH * SL * KCAT * 2 / 16]; // 12.6 MiB
__device__ uint4  g_kcat4[(size_t)NBH * SL * KCAT * 2 / 16];

__device__ __forceinline__ uint32_t smem_u32(const void* p) {
    uint32_t a;
    asm("{ .reg .u64 t; cvta.to.shared.u64 t, %1; cvt.u32.u64 %0, t; }"
        : "=r"(a) : "l"(p));
    return a;
}
#define CP16(d, s) asm volatile("cp.async.cg.shared.global [%0], [%1], 16;" :: "r"(d), "l"(s) : "memory")
#define CP_COMMIT() asm volatile("cp.async.commit_group;" ::: "memory")
#define CP_WAIT(n)  asm volatile("cp.async.wait_group %0;" :: "n"(n) : "memory")
#define LDSM_X4(r, a)                                                          \
    asm volatile("ldmatrix.sync.aligned.m8n8.x4.shared.b16 {%0,%1,%2,%3}, [%4];" \
        : "=r"((r)[0]), "=r"((r)[1]), "=r"((r)[2]), "=r"((r)[3]) : "r"(a))

__device__ __forceinline__ void mma_bf16(float* c, const uint32_t* a,
                                         uint32_t b0, uint32_t b1) {
    asm volatile(
        "mma.sync.aligned.m16n8k16.row.col.f32.bf16.bf16.f32 "
        "{%0,%1,%2,%3}, {%4,%5,%6,%7}, {%8,%9}, {%0,%1,%2,%3};"
        : "+f"(c[0]), "+f"(c[1]), "+f"(c[2]), "+f"(c[3])
        : "r"(a[0]), "r"(a[1]), "r"(a[2]), "r"(a[3]), "r"(b0), "r"(b1));
}

// ---------------------------------------------------------------------------
// prep: build bf16 concat tensors
// ---------------------------------------------------------------------------
__global__ void __launch_bounds__(256)
prep_kernel(const float* __restrict__ q, const float* __restrict__ k)
{
    int gid = blockIdx.x * 256 + threadIdx.x;       // 0..524287
    int tensor = gid >> 18;
    int rem = gid & ((1 << 18) - 1);
    int r = rem >> 3, g = rem & 7;
    const float* src = (tensor ? k : q) + (size_t)r * DD + g * 8;
    __nv_bfloat16* dst = (__nv_bfloat16*)(tensor ? g_kcat4 : g_qcat4) + (size_t)r * KCAT;

    float4 a = ((const float4*)src)[0];
    float4 b = ((const float4*)src)[1];
    float xs[8] = {a.x, a.y, a.z, a.w, b.x, b.y, b.z, b.w};
    __align__(16) __nv_bfloat16 hi[8], lo[8];
#pragma unroll
    for (int i = 0; i < 8; i++) {
        hi[i] = __float2bfloat16(xs[i]);
        lo[i] = __float2bfloat16(xs[i] - __bfloat162float(hi[i]));
    }
    *(uint4*)(dst + g * 8) = *(const uint4*)hi;
    if (tensor == 0) {   // Q: [hi | hi | lo]
        *(uint4*)(dst + 64 + g * 8)  = *(const uint4*)hi;
        *(uint4*)(dst + 128 + g * 8) = *(const uint4*)lo;
    } else {             // K: [hi | lo | hi]
        *(uint4*)(dst + 64 + g * 8)  = *(const uint4*)lo;
        *(uint4*)(dst + 128 + g * 8) = *(const uint4*)hi;
    }
}

// ---------------------------------------------------------------------------
// k1: HMMA scores GEMM. CTA = 128 queries x 2048 keys (16 chunks of 128).
//     smem: A tile 128xRB, K double buffer 2 x 128xRB  (150 KB)
// ---------------------------------------------------------------------------
#define NT1 256
#define OFF_A  0
#define OFF_K0 (128 * RB)
#define OFF_K1 (2 * 128 * RB)
#define SMEM1_TOTAL (3 * 128 * RB)

__global__ void __launch_bounds__(NT1, 1)
qk_mma_kernel()
{
    extern __shared__ char smem[];
    const uint32_t sb = smem_u32(smem);
    const int tid = threadIdx.x, warp = tid >> 5, lane = tid & 31;

    const int bh = blockIdx.y;
    const int q0 = blockIdx.x * 128;
    float* __restrict__ sc = (float*)g_scores4 + (size_t)bh * SL * SL;
    const uint4* __restrict__ qc = g_qcat4 + ((size_t)bh * SL + q0) * (KCAT / 8);
    const uint4* __restrict__ kc = g_kcat4 + (size_t)bh * SL * (KCAT / 8);

    // prologue: async-load Q tile + K chunk 0 (linear gmem -> strided smem)
#pragma unroll
    for (int u = 0; u < 12; u++) {
        int idx = tid + u * NT1;          // 0..3071
        int row = idx / 24, cc = idx % 24;
        CP16(sb + OFF_A  + row * RB + cc * 16, qc + idx);
        CP16(sb + OFF_K0 + row * RB + cc * 16, kc + idx);
    }
    CP_COMMIT();
    CP_WAIT(0);
    __syncthreads();

    const int wm = warp & 3;   // 4 M-tiles of 32
    const int wn = warp >> 2;  // 2 N-halves of 64

    float acc[2][8][4];
#pragma unroll
    for (int mt = 0; mt < 2; mt++)
#pragma unroll
        for (int nt = 0; nt < 8; nt++)
#pragma unroll
            for (int i = 0; i < 4; i++) acc[mt][nt][i] = 0.f;

    for (int c = 0; c < 16; c++) {
        const uint32_t cur = sb + ((c & 1) ? OFF_K1 : OFF_K0);
        const uint32_t nxt = sb + ((c & 1) ? OFF_K0 : OFF_K1);

        __syncthreads();   // all warps done reading the buffer nxt points at
        if (c < 15) {
            const uint4* src = kc + (size_t)(c + 1) * 128 * (KCAT / 8);
#pragma unroll
            for (int u = 0; u < 12; u++) {
                int idx = tid + u * NT1;
                int row = idx / 24, cc = idx % 24;
                CP16(nxt + row * RB + cc * 16, src + idx);
            }
            CP_COMMIT();
        }
        if (c > 0) {
            if (c < 15) CP_WAIT(1); else CP_WAIT(0);
        }
        __syncthreads();   // cur buffer data visible to all warps

        // ---- 128x128x192 via m16n8k16 ----
#pragma unroll
        for (int ks = 0; ks < 12; ks++) {
            uint32_t a[2][4];
#pragma unroll
            for (int mt = 0; mt < 2; mt++) {
                uint32_t ad = sb + OFF_A +
                    (uint32_t)(wm * 32 + mt * 16 + (lane & 15)) * RB +
                    ks * 32 + (lane >> 4) * 16;
                LDSM_X4(a[mt], ad);
            }
            uint32_t b[2][2][4];   // [quad of 32 n][koct][n-oct]
#pragma unroll
            for (int q2 = 0; q2 < 2; q2++)
#pragma unroll
                for (int ko = 0; ko < 2; ko++) {
                    uint32_t bd = cur +
                        (uint32_t)(wn * 64 + q2 * 32 + lane) * RB +
                        ks * 32 + ko * 16;
                    LDSM_X4(b[q2][ko], bd);
                }
#pragma unroll
            for (int mt = 0; mt < 2; mt++)
#pragma unroll
                for (int nt = 0; nt < 8; nt++)
                    mma_bf16(acc[mt][nt], a[mt],
                             b[nt >> 2][0][nt & 3], b[nt >> 2][1][nt & 3]);
        }

        // ---- epilogue: scale + store fragments, reset accum ----
#pragma unroll
        for (int mt = 0; mt < 2; mt++)
#pragma unroll
            for (int nt = 0; nt < 8; nt++) {
                int row = q0 + wm * 32 + mt * 16 + (lane >> 2);
                int col = c * 128 + wn * 64 + nt * 8 + (lane & 3) * 2;
                float2 v0 = make_float2(acc[mt][nt][0] * 0.125f,
                                        acc[mt][nt][1] * 0.125f);
                float2 v1 = make_float2(acc[mt][nt][2] * 0.125f,
                                        acc[mt][nt][3] * 0.125f);
                *(float2*)&sc[(size_t)row * SL + col] = v0;
                *(float2*)&sc[(size_t)(row + 8) * SL + col] = v1;
                acc[mt][nt][0] = 0.f; acc[mt][nt][1] = 0.f;
                acc[mt][nt][2] = 0.f; acc[mt][nt][3] = 0.f;
            }
    }
}

// ---------------------------------------------------------------------------
// k2: entmax + sparse P*V. 2 warps per row, 4 rows per CTA.
// ---------------------------------------------------------------------------
#define NEWT  8
#define NCF   2
#define CAPL2 192

__global__ void __launch_bounds__(256, 3)
entmax_pv2_kernel(const float* __restrict__ v, float* __restrict__ out)
{
    __shared__ float red[4][2][4];
    __shared__ float sp[8][CAPL2];
    __shared__ int   si[8][CAPL2];
    __shared__ float oacc[4][64];
    __shared__ float psum_s[4][2];

    const int tid = threadIdx.x, warp = tid >> 5, lane = tid & 31;
    const int pr = warp >> 1, h = warp & 1;
    const int grow = blockIdx.x * 4 + pr;
    const int bh = grow >> 11, qi = grow & (SL - 1);
    const float* __restrict__ srow = (const float*)g_scores4 + ((size_t)bh * SL + qi) * SL;
    const float* __restrict__ vb = v + (size_t)bh * SL * DD;

    // load 1024 scores per warp (32/lane); x[4j+c] <-> col (j*64+h*32+lane)*4+c
    float x[32];
    float mx = -1e30f;
#pragma unroll
    for (int j = 0; j < 8; j++) {
        float4 t = ((const float4*)srow)[j * 64 + h * 32 + lane];
        x[4 * j + 0] = t.x; x[4 * j + 1] = t.y;
        x[4 * j + 2] = t.z; x[4 * j + 3] = t.w;
        mx = fmaxf(mx, fmaxf(fmaxf(t.x, t.y), fmaxf(t.z, t.w)));
    }
#pragma unroll
    for (int o = 16; o; o >>= 1)
        mx = fmaxf(mx, __shfl_xor_sync(0xffffffffu, mx, o));
    if (lane == 0) red[pr][h][0] = mx;
    __syncthreads();
    mx = fmaxf(red[pr][0][0], red[pr][1][0]);
#pragma unroll
    for (int j = 0; j < 32; j++) x[j] = (x[j] - mx) * 0.5f;

    // Newton from below (tau0=-1 -> f >= 1, monotone convergence)
    float tau = -1.0f;
    for (int it = 0; it < NEWT; it++) {
        float f = 0.f, g = 0.f;
#pragma unroll
        for (int j = 0; j < 32; j++) {
            float m = fmaxf(x[j] - tau, 0.f);
            f = fmaf(m, m, f); g += m;
        }
#pragma unroll
        for (int o = 16; o; o >>= 1) {
            f += __shfl_xor_sync(0xffffffffu, f, o);
            g += __shfl_xor_sync(0xffffffffu, g, o);
        }
        __syncthreads();
        if (lane == 0) { red[pr][h][0] = f; red[pr][h][1] = g; }
        __syncthreads();
        f = red[pr][0][0] + red[pr][1][0];
        g = red[pr][0][1] + red[pr][1][1];
        tau += (f - 1.0f) / fmaxf(2.0f * g, 1e-20f);
    }

    // closed-form refinement on the current support (exact fixed point)
    for (int p = 0; p < NCF; p++) {
        float n = 0.f, s = 0.f, qq = 0.f;
#pragma unroll
        for (int j = 0; j < 32; j++) {
            if (x[j] > tau) { n += 1.f; s += x[j]; qq = fmaf(x[j], x[j], qq); }
        }
#pragma unroll
        for (int o = 16; o; o >>= 1) {
            n  += __shfl_xor_sync(0xffffffffu, n, o);
            s  += __shfl_xor_sync(0xffffffffu, s, o);
            qq += __shfl_xor_sync(0xffffffffu, qq, o);
        }
        __syncthreads();
        if (lane == 0) { red[pr][h][0] = n; red[pr][h][1] = s; red[pr][h][2] = qq; }
        __syncthreads();
        n  = red[pr][0][0] + red[pr][1][0];
        s  = red[pr][0][1] + red[pr][1][1];
        qq = red[pr][0][2] + red[pr][1][2];
        float disc = fmaxf(s * s - n * (qq - 1.0f), 0.f);
        tau = (s - sqrtf(disc)) / fmaxf(n, 1.0f);
    }

    // support extraction (batched smem list) + V gather
    float acc0 = 0.f, acc1 = 0.f, ps = 0.f;
    const unsigned lt = (1u << lane) - 1u;
    int off = 0;
#pragma unroll 4
    for (int j = 0; j < 32; j++) {
        float m = x[j] - tau;
        bool act = (m > 0.f);
        unsigned mask = __ballot_sync(0xffffffffu, act);
        int cnt = __popc(mask);
        if (off + cnt > CAPL2) {
            __syncwarp();
            for (int t = 0; t < off; t++) {
                float pv = sp[warp][t];
                int key = si[warp][t];
                acc0 = fmaf(pv, vb[key * DD + lane], acc0);
                acc1 = fmaf(pv, vb[key * DD + 32 + lane], acc1);
            }
            __syncwarp();
            off = 0;
        }
        if (act) {
            int pos = off + __popc(mask & lt);
            float pv = m * m;
            sp[warp][pos] = pv;
            si[warp][pos] = (j >> 2) * 256 + h * 128 + lane * 4 + (j & 3);
            ps += pv;
        }
        off += cnt;
    }
    __syncwarp();
    for (int t = 0; t < off; t++) {
        float pv = sp[warp][t];
        int key = si[warp][t];
        acc0 = fmaf(pv, vb[key * DD + lane], acc0);
        acc1 = fmaf(pv, vb[key * DD + 32 + lane], acc1);
    }

    // sum(p) renormalization (first-order tau error cancellation)
#pragma unroll
    for (int o = 16; o; o >>= 1)
        ps += __shfl_xor_sync(0xffffffffu, ps, o);
    __syncthreads();
    if (lane == 0) psum_s[pr][h] = ps;
    if (h == 1) { oacc[pr][lane] = acc0; oacc[pr][lane + 32] = acc1; }
    __syncthreads();
    if (h == 0) {
        float inv = 1.0f / fmaxf(psum_s[pr][0] + psum_s[pr][1], 1e-20f);
        float* orow = out + ((size_t)bh * SL + qi) * DD;
        orow[lane]      = (acc0 + oacc[pr][lane]) * inv;
        orow[lane + 32] = (acc1 + oacc[pr][lane + 32]) * inv;
    }
}

// ---------------------------------------------------------------------------
extern "C" void kernel_launch(void* const* d_in, const int* in_sizes, int n_in,
                              void* d_out, int out_size)
{
    const float* q = (const float*)d_in[0];
    const float* k = (const float*)d_in[1];
    const float* v = (const float*)d_in[2];
    float* out = (float*)d_out;

    prep_kernel<<<2048, 256>>>(q, k);

    cudaFuncSetAttribute(qk_mma_kernel,
                         cudaFuncAttributeMaxDynamicSharedMemorySize, SMEM1_TOTAL);
    dim3 g1(SL / 128, NBH);
    qk_mma_kernel<<<g1, NT1, SMEM1_TOTAL>>>();

    entmax_pv2_kernel<<<(NBH * SL) / 4, 256>>>(v, out);
}

// round 7
// speedup vs baseline: 3.2829x; 1.1850x over previous
#include <cuda_runtime.h>
#include <cuda_bf16.h>
#include <cstdint>

// entmax-1.5 attention, B=2 H=8 S=2048 D=64 fp32.
//  prep: Q,K fp32 -> bf16 hi/lo concat (K=192: [Qh|Qh|Ql] x [Kh|Kl|Kh])
//  k1:   HMMA bf16 GEMM; fused candidate filter (s > rowmax-2) -> g_cand
//        (deterministic prefix-scan append positions)
//  k2:   per-row entmax on candidates (Newton + closed-form) + sparse P*V

#define SL   2048
#define DD   64
#define NBH  16
#define KCAT 192
#define RB   400

__device__ float2 g_cand[(size_t)NBH * SL * SL];             // 512 MiB (hard bound)
__device__ int    g_cnt[NBH * SL];
__device__ uint4  g_qcat4[(size_t)NBH * SL * KCAT * 2 / 16]; // 12.6 MiB
__device__ uint4  g_kcat4[(size_t)NBH * SL * KCAT * 2 / 16];

__device__ __forceinline__ uint32_t smem_u32(const void* p) {
    uint32_t a;
    asm("{ .reg .u64 t; cvta.to.shared.u64 t, %1; cvt.u32.u64 %0, t; }"
        : "=r"(a) : "l"(p));
    return a;
}
#define CP16(d, s) asm volatile("cp.async.cg.shared.global [%0], [%1], 16;" :: "r"(d), "l"(s) : "memory")
#define CP_COMMIT() asm volatile("cp.async.commit_group;" ::: "memory")
#define CP_WAIT(n)  asm volatile("cp.async.wait_group %0;" :: "n"(n) : "memory")
#define LDSM_X4(r, a)                                                          \
    asm volatile("ldmatrix.sync.aligned.m8n8.x4.shared.b16 {%0,%1,%2,%3}, [%4];" \
        : "=r"((r)[0]), "=r"((r)[1]), "=r"((r)[2]), "=r"((r)[3]) : "r"(a))

__device__ __forceinline__ void mma_bf16(float* c, const uint32_t* a,
                                         uint32_t b0, uint32_t b1) {
    asm volatile(
        "mma.sync.aligned.m16n8k16.row.col.f32.bf16.bf16.f32 "
        "{%0,%1,%2,%3}, {%4,%5,%6,%7}, {%8,%9}, {%0,%1,%2,%3};"
        : "+f"(c[0]), "+f"(c[1]), "+f"(c[2]), "+f"(c[3])
        : "r"(a[0]), "r"(a[1]), "r"(a[2]), "r"(a[3]), "r"(b0), "r"(b1));
}

// order-preserving float<->uint encoding for atomicMax
__device__ __forceinline__ unsigned encf(float x) {
    unsigned u = __float_as_uint(x);
    return u ^ (unsigned)(((int)u >> 31) | 0x80000000);
}
__device__ __forceinline__ float decf(unsigned e) {
    unsigned u = (e & 0x80000000u) ? (e ^ 0x80000000u) : ~e;
    return __uint_as_float(u);
}

// ---------------------------------------------------------------------------
// prep: build bf16 concat tensors
// ---------------------------------------------------------------------------
__global__ void __launch_bounds__(256)
prep_kernel(const float* __restrict__ q, const float* __restrict__ k)
{
    int gid = blockIdx.x * 256 + threadIdx.x;
    int tensor = gid >> 18;
    int rem = gid & ((1 << 18) - 1);
    int r = rem >> 3, g = rem & 7;
    const float* src = (tensor ? k : q) + (size_t)r * DD + g * 8;
    __nv_bfloat16* dst = (__nv_bfloat16*)(tensor ? g_kcat4 : g_qcat4) + (size_t)r * KCAT;

    float4 a = ((const float4*)src)[0];
    float4 b = ((const float4*)src)[1];
    float xs[8] = {a.x, a.y, a.z, a.w, b.x, b.y, b.z, b.w};
    __align__(16) __nv_bfloat16 hi[8], lo[8];
#pragma unroll
    for (int i = 0; i < 8; i++) {
        hi[i] = __float2bfloat16(xs[i]);
        lo[i] = __float2bfloat16(xs[i] - __bfloat162float(hi[i]));
    }
    *(uint4*)(dst + g * 8) = *(const uint4*)hi;
    if (tensor == 0) {
        *(uint4*)(dst + 64 + g * 8)  = *(const uint4*)hi;
        *(uint4*)(dst + 128 + g * 8) = *(const uint4*)lo;
    } else {
        *(uint4*)(dst + 64 + g * 8)  = *(const uint4*)lo;
        *(uint4*)(dst + 128 + g * 8) = *(const uint4*)hi;
    }
}

// ---------------------------------------------------------------------------
// k1: HMMA GEMM + fused candidate filter. CTA = 128 q x 2048 keys.
// ---------------------------------------------------------------------------
#define NT1 256
#define OFF_A  0
#define OFF_K0 (128 * RB)
#define OFF_K1 (2 * 128 * RB)
#define SMEM1_TOTAL (3 * 128 * RB)

__global__ void __launch_bounds__(NT1, 1)
qk_mma_kernel()
{
    extern __shared__ char smem[];
    __shared__ unsigned s_runmax[128];
    __shared__ int s_cnt[128];
    __shared__ int s_part[128][9];

    const uint32_t sb = smem_u32(smem);
    const int tid = threadIdx.x, warp = tid >> 5, lane = tid & 31;

    const int bh = blockIdx.y;
    const int q0 = blockIdx.x * 128;
    const size_t rid0 = (size_t)bh * SL + q0;
    const uint4* __restrict__ qc = g_qcat4 + rid0 * (KCAT / 8);
    const uint4* __restrict__ kc = g_kcat4 + (size_t)bh * SL * (KCAT / 8);

    if (tid < 128) { s_runmax[tid] = encf(-3e38f); s_cnt[tid] = 0; }

#pragma unroll
    for (int u = 0; u < 12; u++) {
        int idx = tid + u * NT1;
        int row = idx / 24, cc = idx % 24;
        CP16(sb + OFF_A  + row * RB + cc * 16, qc + idx);
        CP16(sb + OFF_K0 + row * RB + cc * 16, kc + idx);
    }
    CP_COMMIT();
    CP_WAIT(0);
    __syncthreads();

    const int wm = warp & 3;
    const int wn = warp >> 2;
    const int oid = wn * 4 + (lane & 3);

    float acc[2][8][4];
#pragma unroll
    for (int mt = 0; mt < 2; mt++)
#pragma unroll
        for (int nt = 0; nt < 8; nt++)
#pragma unroll
            for (int i = 0; i < 4; i++) acc[mt][nt][i] = 0.f;

    for (int c = 0; c < 16; c++) {
        const uint32_t cur = sb + ((c & 1) ? OFF_K1 : OFF_K0);
        const uint32_t nxt = sb + ((c & 1) ? OFF_K0 : OFF_K1);

        __syncthreads();
        if (c < 15) {
            const uint4* src = kc + (size_t)(c + 1) * 128 * (KCAT / 8);
#pragma unroll
            for (int u = 0; u < 12; u++) {
                int idx = tid + u * NT1;
                int row = idx / 24, cc = idx % 24;
                CP16(nxt + row * RB + cc * 16, src + idx);
            }
            CP_COMMIT();
        }
        if (c > 0) {
            if (c < 15) CP_WAIT(1); else CP_WAIT(0);
        }
        __syncthreads();

        // ---- 128x128x192 via m16n8k16 ----
#pragma unroll
        for (int ks = 0; ks < 12; ks++) {
            uint32_t a[2][4];
#pragma unroll
            for (int mt = 0; mt < 2; mt++) {
                uint32_t ad = sb + OFF_A +
                    (uint32_t)(wm * 32 + mt * 16 + (lane & 15)) * RB +
                    ks * 32 + (lane >> 4) * 16;
                LDSM_X4(a[mt], ad);
            }
            uint32_t b[2][2][4];
#pragma unroll
            for (int q2 = 0; q2 < 2; q2++)
#pragma unroll
                for (int ko = 0; ko < 2; ko++) {
                    uint32_t bd = cur +
                        (uint32_t)(wn * 64 + q2 * 32 + lane) * RB +
                        ks * 32 + ko * 16;
                    LDSM_X4(b[q2][ko], bd);
                }
#pragma unroll
            for (int mt = 0; mt < 2; mt++)
#pragma unroll
                for (int nt = 0; nt < 8; nt++)
                    mma_bf16(acc[mt][nt], a[mt],
                             b[nt >> 2][0][nt & 3], b[nt >> 2][1][nt & 3]);
        }

        // ---- fused filter epilogue ----
        // A) per-row running max
#pragma unroll
        for (int mt = 0; mt < 2; mt++)
#pragma unroll
            for (int h = 0; h < 2; h++) {
                float m = -3e38f;
#pragma unroll
                for (int nt = 0; nt < 8; nt++)
                    m = fmaxf(m, fmaxf(acc[mt][nt][h * 2], acc[mt][nt][h * 2 + 1]));
                int lr = wm * 32 + mt * 16 + h * 8 + (lane >> 2);
                atomicMax(&s_runmax[lr], encf(m * 0.125f));
            }
        __syncthreads();

        // B) predicate + per-owner counts
        unsigned pm[2][2];
#pragma unroll
        for (int mt = 0; mt < 2; mt++)
#pragma unroll
            for (int h = 0; h < 2; h++) {
                int lr = wm * 32 + mt * 16 + h * 8 + (lane >> 2);
                float thr = decf(s_runmax[lr]) - 2.0f;
                unsigned msk = 0;
#pragma unroll
                for (int nt = 0; nt < 8; nt++)
#pragma unroll
                    for (int ic = 0; ic < 2; ic++)
                        if (acc[mt][nt][h * 2 + ic] * 0.125f > thr)
                            msk |= 1u << (nt * 2 + ic);
                pm[mt][h] = msk;
                s_part[lr][oid] = __popc(msk);
            }
        __syncthreads();

        // C) deterministic per-row prefix over 8 owners
        if (tid < 128) {
            int b = s_cnt[tid];
#pragma unroll
            for (int o = 0; o < 8; o++) {
                int t = s_part[tid][o];
                s_part[tid][o] = b;
                b += t;
            }
            s_cnt[tid] = b;
        }
        __syncthreads();

        // D) append candidates at deterministic positions
#pragma unroll
        for (int mt = 0; mt < 2; mt++)
#pragma unroll
            for (int h = 0; h < 2; h++) {
                int lr = wm * 32 + mt * 16 + h * 8 + (lane >> 2);
                unsigned msk = pm[mt][h];
                int pos = s_part[lr][oid];
                size_t base = (rid0 + lr) * (size_t)SL;
#pragma unroll
                for (int nt = 0; nt < 8; nt++)
#pragma unroll
                    for (int ic = 0; ic < 2; ic++) {
                        if (msk & (1u << (nt * 2 + ic))) {
                            int col = c * 128 + wn * 64 + nt * 8 + (lane & 3) * 2 + ic;
                            g_cand[base + pos] = make_float2(
                                acc[mt][nt][h * 2 + ic] * 0.125f,
                                __int_as_float(col));
                            pos++;
                        }
                        acc[mt][nt][h * 2 + ic] = 0.f;
                    }
            }
    }

    __syncthreads();
    if (tid < 128) g_cnt[rid0 + tid] = s_cnt[tid];
}

// ---------------------------------------------------------------------------
// k2: entmax on candidates + sparse P*V. One warp per row.
// ---------------------------------------------------------------------------
#define NEWT 8
#define NCF  3
#define CAPL 128
#define REGC 32           // 32 regs/lane -> 1024 candidates in registers

__global__ void __launch_bounds__(256, 3)
entmax_pv3_kernel(const float* __restrict__ v, float* __restrict__ out)
{
    __shared__ float sp[8][CAPL];
    __shared__ int   si[8][CAPL];

    const int tid = threadIdx.x, warp = tid >> 5, lane = tid & 31;
    const int rid = blockIdx.x * 8 + warp;
    const int cnt = g_cnt[rid];
    const float2* __restrict__ cand = g_cand + (size_t)rid * SL;
    const float* __restrict__ vb = v + (size_t)(rid >> 11) * SL * DD;

    float xs[REGC];
#pragma unroll
    for (int j = 0; j < REGC; j++) {
        int idx = j * 32 + lane;
        xs[j] = (idx < cnt) ? cand[idx].x : -1e30f;
    }
    const bool big = (cnt > REGC * 32);

    float mx = -3e38f;
#pragma unroll
    for (int j = 0; j < REGC; j++) mx = fmaxf(mx, xs[j]);
    if (big)
        for (int idx = REGC * 32 + lane; idx < cnt; idx += 32)
            mx = fmaxf(mx, cand[idx].x);
#pragma unroll
    for (int o = 16; o; o >>= 1)
        mx = fmaxf(mx, __shfl_xor_sync(0xffffffffu, mx, o));
#pragma unroll
    for (int j = 0; j < REGC; j++) xs[j] = (xs[j] - mx) * 0.5f;

    // Newton from below (tau0 = -1 guarantees f >= 1)
    float tau = -1.0f;
    for (int it = 0; it < NEWT; it++) {
        float f = 0.f, g = 0.f;
#pragma unroll
        for (int j = 0; j < REGC; j++) {
            float m = fmaxf(xs[j] - tau, 0.f);
            f = fmaf(m, m, f); g += m;
        }
        if (big)
            for (int idx = REGC * 32 + lane; idx < cnt; idx += 32) {
                float xv = (cand[idx].x - mx) * 0.5f;
                float m = fmaxf(xv - tau, 0.f);
                f = fmaf(m, m, f); g += m;
            }
#pragma unroll
        for (int o = 16; o; o >>= 1) {
            f += __shfl_xor_sync(0xffffffffu, f, o);
            g += __shfl_xor_sync(0xffffffffu, g, o);
        }
        tau += (f - 1.0f) / fmaxf(2.0f * g, 1e-20f);
    }

    // closed-form refinement on current support (exact fixed point)
    for (int p = 0; p < NCF; p++) {
        float n = 0.f, s = 0.f, qq = 0.f;
#pragma unroll
        for (int j = 0; j < REGC; j++) {
            if (xs[j] > tau) { n += 1.f; s += xs[j]; qq = fmaf(xs[j], xs[j], qq); }
        }
        if (big)
            for (int idx = REGC * 32 + lane; idx < cnt; idx += 32) {
                float xv = (cand[idx].x - mx) * 0.5f;
                if (xv > tau) { n += 1.f; s += xv; qq = fmaf(xv, xv, qq); }
            }
#pragma unroll
        for (int o = 16; o; o >>= 1) {
            n  += __shfl_xor_sync(0xffffffffu, n, o);
            s  += __shfl_xor_sync(0xffffffffu, s, o);
            qq += __shfl_xor_sync(0xffffffffu, qq, o);
        }
        float disc = fmaxf(s * s - n * (qq - 1.0f), 0.f);
        tau = (s - sqrtf(disc)) / fmaxf(n, 1.0f);
    }

    // support extraction (ballot-compacted, deterministic order) + V gather
    float acc0 = 0.f, acc1 = 0.f, ps = 0.f;
    const unsigned lt = (1u << lane) - 1u;
    int off = 0;

#pragma unroll 4
    for (int j = 0; j < REGC; j++) {
        float m = xs[j] - tau;
        bool act = (m > 0.f);
        unsigned mask = __ballot_sync(0xffffffffu, act);
        int c = __popc(mask);
        if (off + c > CAPL) {
            __syncwarp();
            for (int t = 0; t < off; t++) {
                float pv = sp[warp][t];
                int key = si[warp][t];
                acc0 = fmaf(pv, vb[key * DD + lane], acc0);
                acc1 = fmaf(pv, vb[key * DD + 32 + lane], acc1);
            }
            __syncwarp();
            off = 0;
        }
        if (act) {
            int pos = off + __popc(mask & lt);
            float pv = m * m;
            sp[warp][pos] = pv;
            si[warp][pos] = __float_as_int(cand[j * 32 + lane].y);
            ps += pv;
        }
        off += c;
    }
    if (big) {
        for (int bix = REGC * 32; bix < cnt; bix += 32) {
            int idx = bix + lane;
            bool valid = idx < cnt;
            float2 t2 = valid ? cand[idx] : make_float2(-1e30f, 0.f);
            float m = (t2.x - mx) * 0.5f - tau;
            bool act = valid && (m > 0.f);
            unsigned mask = __ballot_sync(0xffffffffu, act);
            int c = __popc(mask);
            if (off + c > CAPL) {
                __syncwarp();
                for (int t = 0; t < off; t++) {
                    float pv = sp[warp][t];
                    int key = si[warp][t];
                    acc0 = fmaf(pv, vb[key * DD + lane], acc0);
                    acc1 = fmaf(pv, vb[key * DD + 32 + lane], acc1);
                }
                __syncwarp();
                off = 0;
            }
            if (act) {
                int pos = off + __popc(mask & lt);
                float pv = m * m;
                sp[warp][pos] = pv;
                si[warp][pos] = __float_as_int(t2.y);
                ps += pv;
            }
            off += c;
        }
    }
    __syncwarp();
    for (int t = 0; t < off; t++) {
        float pv = sp[warp][t];
        int key = si[warp][t];
        acc0 = fmaf(pv, vb[key * DD + lane], acc0);
        acc1 = fmaf(pv, vb[key * DD + 32 + lane], acc1);
    }

    // renormalize (first-order tau error cancellation)
#pragma unroll
    for (int o = 16; o; o >>= 1)
        ps += __shfl_xor_sync(0xffffffffu, ps, o);
    float inv = 1.0f / fmaxf(ps, 1e-20f);

    float* orow = out + (size_t)rid * DD;
    orow[lane]      = acc0 * inv;
    orow[lane + 32] = acc1 * inv;
}

// ---------------------------------------------------------------------------
extern "C" void kernel_launch(void* const* d_in, const int* in_sizes, int n_in,
                              void* d_out, int out_size)
{
    const float* q = (const float*)d_in[0];
    const float* k = (const float*)d_in[1];
    const float* v = (const float*)d_in[2];
    float* out = (float*)d_out;

    prep_kernel<<<2048, 256>>>(q, k);

    cudaFuncSetAttribute(qk_mma_kernel,
                         cudaFuncAttributeMaxDynamicSharedMemorySize, SMEM1_TOTAL);
    dim3 g1(SL / 128, NBH);
    qk_mma_kernel<<<g1, NT1, SMEM1_TOTAL>>>();

    entmax_pv3_kernel<<<(NBH * SL) / 8, 256>>>(v, out);
}